// round 5
// baseline (speedup 1.0000x reference)
#include <cuda_runtime.h>
#include <math.h>

#define BATCHN 2048
#define SEQN   512
#define INPN   128
#define HIDN   256
#define OUTN   64
#define KTOT   384
#define ROWS   8           // batch rows per CTA (2 CTAs co-resident per SM)
#define NTHR   256
#define CSS    12          // cs row stride (floats): mult of 4 for LDS.128
#define FEPS   1e-8f

typedef unsigned long long u64t;

__device__ float g_Wcat[KTOT * HIDN];                   // [384][256] lambda-folded
__device__ float g_H[(size_t)BATCHN * SEQN * HIDN];     // h history (1 GB scratch)

__device__ __forceinline__ u64t dup2(float a) {
    u64t r; asm("mov.b64 %0, {%1, %1};" : "=l"(r) : "f"(a)); return r;
}
__device__ __forceinline__ void ffma2(u64t& d, u64t a, u64t b) {
    asm("fma.rn.f32x2 %0, %1, %2, %0;" : "+l"(d) : "l"(a), "l"(b));
}
__device__ __forceinline__ float lo2(u64t v) { return __uint_as_float((unsigned)v); }
__device__ __forceinline__ float hi2(u64t v) { return __uint_as_float((unsigned)(v >> 32)); }

__device__ __forceinline__ float wsum(float v) {
    v += __shfl_xor_sync(0xffffffffu, v, 16);
    v += __shfl_xor_sync(0xffffffffu, v, 8);
    v += __shfl_xor_sync(0xffffffffu, v, 4);
    v += __shfl_xor_sync(0xffffffffu, v, 2);
    v += __shfl_xor_sync(0xffffffffu, v, 1);
    return v;
}

__global__ void prep_kernel(const float* __restrict__ Win, const float* __restrict__ Wrec,
                            const float* __restrict__ li,  const float* __restrict__ lr) {
    int k = blockIdx.x, j = threadIdx.x;
    g_Wcat[k * HIDN + j] = (k < HIDN) ? lr[j] * Wrec[k * HIDN + j]
                                      : li[j] * Win[(k - HIDN) * HIDN + j];
}

__global__ void __launch_bounds__(NTHR, 2) nlnn_main(
    const float* __restrict__ x,         // [B,S,128]
    const float* __restrict__ h_init,    // [B,256]
    const float* __restrict__ alpha_raw, // [256]
    float* __restrict__ hfin)
{
    extern __shared__ float smem[];
    float* cs    = smem;                 // [384][CSS]: k<256 h, k>=256 x
    float* vpart = smem + KTOT * CSS;    // [4][8][256]

    const int tid = threadIdx.x;
    const int b0  = blockIdx.x * ROWS;

    // GEMM mapping: 64 col-groups (4 cols) x 4 K-quarters; every thread does all 8 rows
    const int jg = tid & 63, kg = tid >> 6;
    const int j4 = jg * 4;
    const int kbeg = kg * 96;

    const int w = tid >> 5, lane = tid & 31;   // warp w <-> batch row w

    float hh[8], al[8];
#pragma unroll
    for (int i = 0; i < 8; ++i) {
        int j = lane + 32 * i;
        hh[i] = h_init[(size_t)(b0 + w) * HIDN + j];
        al[i] = 1.0f / (1.0f + expf(-alpha_raw[j]));
        cs[j * CSS + w] = hh[i];
    }

    float xr[4];
#pragma unroll
    for (int i = 0; i < 4; ++i)
        xr[i] = x[(size_t)(b0 + w) * SEQN * INPN + lane + 32 * i];

    for (int t = 0; t < SEQN; ++t) {
#pragma unroll
        for (int i = 0; i < 4; ++i)
            cs[(HIDN + lane + 32 * i) * CSS + w] = xr[i];
        __syncthreads();                                   // S1: cs complete

        // ---- phase A: 8 rows x 4 cols, this thread's K-quarter ----
        u64t acc[4][4];
#pragma unroll
        for (int p = 0; p < 4; ++p)
#pragma unroll
            for (int c = 0; c < 4; ++c) acc[p][c] = 0ull;

        const float* wp = g_Wcat + (size_t)kbeg * HIDN + j4;
        const float* cp = cs + kbeg * CSS;
#pragma unroll 8
        for (int kk = 0; kk < 96; ++kk) {
            float4 wv = *(const float4*)(wp + (size_t)kk * HIDN);
            ulonglong2 ha = *(const ulonglong2*)(cp + kk * CSS);     // rows 0..3
            ulonglong2 hb = *(const ulonglong2*)(cp + kk * CSS + 4); // rows 4..7
            u64t bx = dup2(wv.x), by = dup2(wv.y), bz = dup2(wv.z), bw = dup2(wv.w);
            ffma2(acc[0][0], ha.x, bx); ffma2(acc[0][1], ha.x, by);
            ffma2(acc[0][2], ha.x, bz); ffma2(acc[0][3], ha.x, bw);
            ffma2(acc[1][0], ha.y, bx); ffma2(acc[1][1], ha.y, by);
            ffma2(acc[1][2], ha.y, bz); ffma2(acc[1][3], ha.y, bw);
            ffma2(acc[2][0], hb.x, bx); ffma2(acc[2][1], hb.x, by);
            ffma2(acc[2][2], hb.x, bz); ffma2(acc[2][3], hb.x, bw);
            ffma2(acc[3][0], hb.y, bx); ffma2(acc[3][1], hb.y, by);
            ffma2(acc[3][2], hb.y, bz); ffma2(acc[3][3], hb.y, bw);
        }
        {
            float* vp = vpart + (size_t)(kg * ROWS) * HIDN + j4;
#pragma unroll
            for (int p = 0; p < 4; ++p) {
                *(float4*)(vp + (size_t)(2 * p) * HIDN) =
                    make_float4(lo2(acc[p][0]), lo2(acc[p][1]), lo2(acc[p][2]), lo2(acc[p][3]));
                *(float4*)(vp + (size_t)(2 * p + 1) * HIDN) =
                    make_float4(hi2(acc[p][0]), hi2(acc[p][1]), hi2(acc[p][2]), hi2(acc[p][3]));
            }
        }
        __syncthreads();                                   // S2: partials ready

        // ---- phase B: warp w owns row w ----
        float vv[8], ssq = 0.f;
#pragma unroll
        for (int i = 0; i < 8; ++i) {
            int j = lane + 32 * i;
            float s = vpart[(0 * ROWS + w) * HIDN + j]
                    + vpart[(1 * ROWS + w) * HIDN + j]
                    + vpart[(2 * ROWS + w) * HIDN + j]
                    + vpart[(3 * ROWS + w) * HIDN + j];
            vv[i] = s;
            ssq = fmaf(s, s, ssq);
        }
        ssq = wsum(ssq);
        float ninv = 1.0f / (sqrtf(ssq) + FEPS);

        float hsq = 0.f;
#pragma unroll
        for (int i = 0; i < 8; ++i) hsq = fmaf(hh[i], hh[i], hsq);
        hsq = wsum(hsq);
        float hinv = 1.0f / (sqrtf(hsq) + FEPS);

        float dot = 0.f, hn[8], ht[8];
#pragma unroll
        for (int i = 0; i < 8; ++i) {
            hn[i] = vv[i] * ninv;
            ht[i] = hh[i] * hinv;
            dot = fmaf(ht[i], hn[i], dot);
        }
        dot = wsum(dot);
        dot = fminf(fmaxf(dot, -1.0f + FEPS), 1.0f - FEPS);
        float theta  = acosf(dot);
        float st     = __sinf(theta);
        float inv_st = 1.0f / (st + FEPS);
        bool  mask   = (st > FEPS);

        float res[8], rsq = 0.f;
#pragma unroll
        for (int i = 0; i < 8; ++i) {
            float ct = __sinf((1.0f - al[i]) * theta) * inv_st;
            float cn = __sinf(al[i] * theta) * inv_st;
            float r  = fmaf(ct, ht[i], cn * hn[i]);
            r = mask ? r : hn[i];
            res[i] = r;
            rsq = fmaf(r, r, rsq);
        }
        rsq = wsum(rsq);
        float rinv = 1.0f / (sqrtf(rsq) + FEPS);

        float* hrow = g_H + ((size_t)(b0 + w) * SEQN + t) * HIDN;
#pragma unroll
        for (int i = 0; i < 8; ++i) {
            hh[i] = res[i] * rinv;
            cs[(lane + 32 * i) * CSS + w] = hh[i];   // next step's GEMM operand
            hrow[lane + 32 * i] = hh[i];             // history for out GEMM
        }

        if (t + 1 < SEQN) {
#pragma unroll
            for (int i = 0; i < 4; ++i)
                xr[i] = x[((size_t)(b0 + w) * SEQN + t + 1) * INPN + lane + 32 * i];
        }
        // cs writes are ordered before next phase A by S1 of the next iteration
    }

    if (hfin) {
#pragma unroll
        for (int i = 0; i < 8; ++i)
            hfin[(size_t)(b0 + w) * HIDN + lane + 32 * i] = hh[i];
    }
}

// out[row][c] = s_z * sum_j H[row][j]*Wout[j][c]; row = b*SEQN + t
#define OB_ROWS 64
#define HSTR    68
__global__ void __launch_bounds__(256, 2) nlnn_out(
    const float* __restrict__ Wout, const float* __restrict__ s_z_p,
    float* __restrict__ outp)
{
    extern __shared__ float sh[];                     // [256][HSTR] transposed H tile
    const int tid = threadIdx.x;
    const size_t row0 = (size_t)blockIdx.x * OB_ROWS;

#pragma unroll 8
    for (int i = 0; i < OB_ROWS; ++i)
        sh[tid * HSTR + i] = g_H[(row0 + i) * HIDN + tid];
    __syncthreads();

    const int c = tid & 63, rb = (tid >> 6) * 16;     // 4 groups x 16 rows
    const float sz = s_z_p[0];

    u64t acc[8];
#pragma unroll
    for (int p = 0; p < 8; ++p) acc[p] = 0ull;

#pragma unroll 4
    for (int j = 0; j < HIDN; ++j) {
        u64t b = dup2(Wout[j * OUTN + c]);
        const float* hp = sh + j * HSTR + rb;
        ulonglong2 hA = *(const ulonglong2*)(hp);
        ulonglong2 hB = *(const ulonglong2*)(hp + 4);
        ulonglong2 hC = *(const ulonglong2*)(hp + 8);
        ulonglong2 hD = *(const ulonglong2*)(hp + 12);
        ffma2(acc[0], hA.x, b); ffma2(acc[1], hA.y, b);
        ffma2(acc[2], hB.x, b); ffma2(acc[3], hB.y, b);
        ffma2(acc[4], hC.x, b); ffma2(acc[5], hC.y, b);
        ffma2(acc[6], hD.x, b); ffma2(acc[7], hD.y, b);
    }
#pragma unroll
    for (int p = 0; p < 8; ++p) {
        size_t r = row0 + rb + 2 * p;
        outp[r * OUTN + c]       = sz * lo2(acc[p]);
        outp[(r + 1) * OUTN + c] = sz * hi2(acc[p]);
    }
}

extern "C" void kernel_launch(void* const* d_in, const int* in_sizes, int n_in,
                              void* d_out, int out_size) {
    const float* x      = (const float*)d_in[0];
    const float* h_init = (const float*)d_in[1];
    const float* Win    = (const float*)d_in[2];
    const float* Wrec   = (const float*)d_in[3];
    const float* Wout   = (const float*)d_in[4];
    const float* li     = (const float*)d_in[5];
    const float* lr     = (const float*)d_in[6];
    const float* sz     = (const float*)d_in[7];
    const float* ar     = (const float*)d_in[8];

    float* outp = (float*)d_out;
    long long main_elems = (long long)BATCHN * SEQN * OUTN;
    float* hfin = nullptr;
    if ((long long)out_size >= main_elems + (long long)BATCHN * HIDN)
        hfin = outp + main_elems;

    int smem_main = (KTOT * CSS + 4 * ROWS * HIDN) * (int)sizeof(float);
    int smem_out  = (HIDN * HSTR) * (int)sizeof(float);
    cudaFuncSetAttribute(nlnn_main, cudaFuncAttributeMaxDynamicSharedMemorySize, smem_main);
    cudaFuncSetAttribute(nlnn_out,  cudaFuncAttributeMaxDynamicSharedMemorySize, smem_out);

    prep_kernel<<<KTOT, HIDN>>>(Win, Wrec, li, lr);
    nlnn_main<<<BATCHN / ROWS, NTHR, smem_main>>>(x, h_init, ar, hfin);
    nlnn_out<<<(BATCHN * SEQN) / OB_ROWS, 256, smem_out>>>(Wout, sz, outp);
}

// round 6
// speedup vs baseline: 1.0331x; 1.0331x over previous
#include <cuda_runtime.h>
#include <math.h>

#define BATCHN 2048
#define SEQN   512
#define INPN   128
#define HIDN   256
#define OUTN   64
#define ROWS   16
#define NTHR   512
#define CSS    20          // smem row stride (floats), 16B-aligned products
#define FEPS   1e-8f

typedef unsigned long long u64t;

__device__ float g_Wr[HIDN * HIDN];                     // lam_r folded Wrec [256][256]
__device__ float g_Wi[INPN * HIDN];                     // lam_i folded Win  [128][256]
__device__ float g_H[(size_t)BATCHN * SEQN * HIDN];     // h history (1 GB scratch)

__device__ __forceinline__ u64t dup2(float a) {
    u64t r; asm("mov.b64 %0, {%1, %1};" : "=l"(r) : "f"(a)); return r;
}
__device__ __forceinline__ void ffma2(u64t& d, u64t a, u64t b) {
    asm("fma.rn.f32x2 %0, %1, %2, %0;" : "+l"(d) : "l"(a), "l"(b));
}
__device__ __forceinline__ float lo2(u64t v) { return __uint_as_float((unsigned)v); }
__device__ __forceinline__ float hi2(u64t v) { return __uint_as_float((unsigned)(v >> 32)); }

__global__ void prep_kernel(const float* __restrict__ Win, const float* __restrict__ Wrec,
                            const float* __restrict__ li,  const float* __restrict__ lr) {
    int k = blockIdx.x, j = threadIdx.x;
    if (k < HIDN) g_Wr[k * HIDN + j] = lr[j] * Wrec[k * HIDN + j];
    else          g_Wi[(k - HIDN) * HIDN + j] = li[j] * Win[(k - HIDN) * HIDN + j];
}

__global__ void __launch_bounds__(NTHR, 1) nlnn_main(
    const float* __restrict__ x,         // [B,S,128]
    const float* __restrict__ h_init,    // [B,256]
    const float* __restrict__ alpha_raw, // [256]
    float* __restrict__ hfin)
{
    extern __shared__ float smem[];
    float* csh  = smem;                          // [256][CSS]  h_t
    float* csx  = csh + HIDN * CSS;              // [128][CSS]  x staged
    float* recp = csx + INPN * CSS;              // [4][16][256]
    float* inpp = recp + 4 * ROWS * HIDN;        // [2][2][16][256] (double-buffered)

    const int tid = threadIdx.x;
    const int b0  = blockIdx.x * ROWS;

    // rec GEMM mapping: 64 jg x 2 rg (8 rows) x 4 kg (64 k each)
    const int jg = tid & 63, rg = (tid >> 6) & 1, kg = tid >> 7;
    const int j4 = jg * 4, r0 = rg * 8, kb = kg * 64;
    // inp GEMM mapping: 64 jg x 4 rgi (4 rows) x 2 kgi (64 k each)
    const int rgi = (tid >> 6) & 3, kgi = tid >> 8;
    const int r0i = rgi * 4, kbi = kgi * 64;

    const int w = tid >> 5, lane = tid & 31;     // warp w <-> batch row w

    float hh[8], al[8];
#pragma unroll
    for (int i = 0; i < 8; ++i) {
        int j = lane + 32 * i;
        hh[i] = h_init[(size_t)(b0 + w) * HIDN + j];
        al[i] = 1.0f / (1.0f + expf(-alpha_raw[j]));
        csh[j * CSS + w] = hh[i];
    }
    // stage x_0
#pragma unroll
    for (int i = 0; i < 4; ++i)
        csx[(lane + 32 * i) * CSS + w] = x[(size_t)(b0 + w) * SEQN * INPN + lane + 32 * i];
    __syncthreads();

    // prologue: inp partials for t=0 into plane 0
    {
        u64t a2[2][4];
#pragma unroll
        for (int p = 0; p < 2; ++p)
#pragma unroll
            for (int c = 0; c < 4; ++c) a2[p][c] = 0ull;
        const float* wp = g_Wi + (size_t)kbi * HIDN + j4;
        const float* cp = csx + kbi * CSS + r0i;
#pragma unroll 8
        for (int kk = 0; kk < 64; ++kk) {
            float4 wv = *(const float4*)(wp + (size_t)kk * HIDN);
            ulonglong2 hx = *(const ulonglong2*)(cp + kk * CSS);
            u64t bx = dup2(wv.x), by = dup2(wv.y), bz = dup2(wv.z), bw = dup2(wv.w);
            ffma2(a2[0][0], hx.x, bx); ffma2(a2[0][1], hx.x, by);
            ffma2(a2[0][2], hx.x, bz); ffma2(a2[0][3], hx.x, bw);
            ffma2(a2[1][0], hx.y, bx); ffma2(a2[1][1], hx.y, by);
            ffma2(a2[1][2], hx.y, bz); ffma2(a2[1][3], hx.y, bw);
        }
        float* ip = inpp + (size_t)(kgi * ROWS + r0i) * HIDN + j4;
#pragma unroll
        for (int p = 0; p < 2; ++p) {
            *(float4*)(ip + (size_t)(2 * p) * HIDN) =
                make_float4(lo2(a2[p][0]), lo2(a2[p][1]), lo2(a2[p][2]), lo2(a2[p][3]));
            *(float4*)(ip + (size_t)(2 * p + 1) * HIDN) =
                make_float4(hi2(a2[p][0]), hi2(a2[p][1]), hi2(a2[p][2]), hi2(a2[p][3]));
        }
    }
    // prefetch x_1
    float xr[4];
#pragma unroll
    for (int i = 0; i < 4; ++i)
        xr[i] = x[((size_t)(b0 + w) * SEQN + 1) * INPN + lane + 32 * i];

    for (int t = 0; t < SEQN; ++t) {
        __syncthreads();                         // S1: csh = h_t; prior csx reads done

        // stage x_{t+1}; prefetch x_{t+2}
#pragma unroll
        for (int i = 0; i < 4; ++i)
            csx[(lane + 32 * i) * CSS + w] = xr[i];
        {
            int tt = (t + 2 < SEQN) ? t + 2 : SEQN - 1;
#pragma unroll
            for (int i = 0; i < 4; ++i)
                xr[i] = x[((size_t)(b0 + w) * SEQN + tt) * INPN + lane + 32 * i];
        }

        // ---- phase A: rec GEMM (K=256), 8 rows x 4 cols x 64 k ----
        u64t acc[4][4];
#pragma unroll
        for (int p = 0; p < 4; ++p)
#pragma unroll
            for (int c = 0; c < 4; ++c) acc[p][c] = 0ull;

        const float* wp = g_Wr + (size_t)kb * HIDN + j4;
        const float* cp = csh + kb * CSS + r0;
#pragma unroll 8
        for (int kk = 0; kk < 64; ++kk) {
            float4 wv = *(const float4*)(wp + (size_t)kk * HIDN);
            ulonglong2 ha = *(const ulonglong2*)(cp + kk * CSS);
            ulonglong2 hb = *(const ulonglong2*)(cp + kk * CSS + 4);
            u64t bx = dup2(wv.x), by = dup2(wv.y), bz = dup2(wv.z), bw = dup2(wv.w);
            ffma2(acc[0][0], ha.x, bx); ffma2(acc[0][1], ha.x, by);
            ffma2(acc[0][2], ha.x, bz); ffma2(acc[0][3], ha.x, bw);
            ffma2(acc[1][0], ha.y, bx); ffma2(acc[1][1], ha.y, by);
            ffma2(acc[1][2], ha.y, bz); ffma2(acc[1][3], ha.y, bw);
            ffma2(acc[2][0], hb.x, bx); ffma2(acc[2][1], hb.x, by);
            ffma2(acc[2][2], hb.x, bz); ffma2(acc[2][3], hb.x, bw);
            ffma2(acc[3][0], hb.y, bx); ffma2(acc[3][1], hb.y, by);
            ffma2(acc[3][2], hb.y, bz); ffma2(acc[3][3], hb.y, bw);
        }
        {
            float* vp = recp + (size_t)(kg * ROWS + r0) * HIDN + j4;
#pragma unroll
            for (int p = 0; p < 4; ++p) {
                *(float4*)(vp + (size_t)(2 * p) * HIDN) =
                    make_float4(lo2(acc[p][0]), lo2(acc[p][1]), lo2(acc[p][2]), lo2(acc[p][3]));
                *(float4*)(vp + (size_t)(2 * p + 1) * HIDN) =
                    make_float4(hi2(acc[p][0]), hi2(acc[p][1]), hi2(acc[p][2]), hi2(acc[p][3]));
            }
        }
        __syncthreads();                         // S2: recp + csx ready

        // ---- phase B part 1: combine + interleaved reductions ----
        const float* ipr = inpp + (size_t)((t & 1) * 2 * ROWS + w) * HIDN;
        float vv[8], ssq = 0.f, hsq = 0.f, dtr = 0.f;
#pragma unroll
        for (int i = 0; i < 8; ++i) {
            int j = lane + 32 * i;
            float s = recp[(0 * ROWS + w) * HIDN + j]
                    + recp[(1 * ROWS + w) * HIDN + j]
                    + recp[(2 * ROWS + w) * HIDN + j]
                    + recp[(3 * ROWS + w) * HIDN + j]
                    + ipr[j] + ipr[ROWS * HIDN + j];
            vv[i] = s;
            ssq = fmaf(s, s, ssq);
            hsq = fmaf(hh[i], hh[i], hsq);
            dtr = fmaf(hh[i], s, dtr);
        }
#pragma unroll
        for (int d = 16; d > 0; d >>= 1) {       // interleaved 3-way tree
            ssq += __shfl_xor_sync(0xffffffffu, ssq, d);
            hsq += __shfl_xor_sync(0xffffffffu, hsq, d);
            dtr += __shfl_xor_sync(0xffffffffu, dtr, d);
        }
        float ninv = 1.0f / (sqrtf(ssq) + FEPS);
        float hinv = 1.0f / (sqrtf(hsq) + FEPS);
        float dot  = dtr * ninv * hinv;
        dot = fminf(fmaxf(dot, -1.0f + FEPS), 1.0f - FEPS);
        float theta  = acosf(dot);
        float st     = __sinf(theta);
        float inv_st = 1.0f / (st + FEPS);
        bool  mask   = (st > FEPS);

        // ---- phase B part 2: inp GEMM for t+1 (fills issue slots under slerp) ----
        if (t + 1 < SEQN) {
            u64t a2[2][4];
#pragma unroll
            for (int p = 0; p < 2; ++p)
#pragma unroll
                for (int c = 0; c < 4; ++c) a2[p][c] = 0ull;
            const float* wip = g_Wi + (size_t)kbi * HIDN + j4;
            const float* cxp = csx + kbi * CSS + r0i;
#pragma unroll 8
            for (int kk = 0; kk < 64; ++kk) {
                float4 wv = *(const float4*)(wip + (size_t)kk * HIDN);
                ulonglong2 hx = *(const ulonglong2*)(cxp + kk * CSS);
                u64t bx = dup2(wv.x), by = dup2(wv.y), bz = dup2(wv.z), bw = dup2(wv.w);
                ffma2(a2[0][0], hx.x, bx); ffma2(a2[0][1], hx.x, by);
                ffma2(a2[0][2], hx.x, bz); ffma2(a2[0][3], hx.x, bw);
                ffma2(a2[1][0], hx.y, bx); ffma2(a2[1][1], hx.y, by);
                ffma2(a2[1][2], hx.y, bz); ffma2(a2[1][3], hx.y, bw);
            }
            float* ip = inpp + (size_t)((((t + 1) & 1) * 2 + kgi) * ROWS + r0i) * HIDN + j4;
#pragma unroll
            for (int p = 0; p < 2; ++p) {
                *(float4*)(ip + (size_t)(2 * p) * HIDN) =
                    make_float4(lo2(a2[p][0]), lo2(a2[p][1]), lo2(a2[p][2]), lo2(a2[p][3]));
                *(float4*)(ip + (size_t)(2 * p + 1) * HIDN) =
                    make_float4(hi2(a2[p][0]), hi2(a2[p][1]), hi2(a2[p][2]), hi2(a2[p][3]));
            }
        }

        // ---- phase B part 3: per-element slerp + renorm ----
        float res[8], rsq = 0.f;
#pragma unroll
        for (int i = 0; i < 8; ++i) {
            float hn = vv[i] * ninv;
            float ht = hh[i] * hinv;
            float ct = __sinf((1.0f - al[i]) * theta) * inv_st;
            float cn = __sinf(al[i] * theta) * inv_st;
            float r  = fmaf(ct, ht, cn * hn);
            r = mask ? r : hn;
            res[i] = r;
            rsq = fmaf(r, r, rsq);
        }
#pragma unroll
        for (int d = 16; d > 0; d >>= 1)
            rsq += __shfl_xor_sync(0xffffffffu, rsq, d);
        float rinv = 1.0f / (sqrtf(rsq) + FEPS);

        float* hrow = g_H + ((size_t)(b0 + w) * SEQN + t) * HIDN;
#pragma unroll
        for (int i = 0; i < 8; ++i) {
            hh[i] = res[i] * rinv;
            csh[(lane + 32 * i) * CSS + w] = hh[i];
            hrow[lane + 32 * i] = hh[i];
        }
        // next S1 orders csh/inpp writes before their readers
    }

    if (hfin) {
#pragma unroll
        for (int i = 0; i < 8; ++i)
            hfin[(size_t)(b0 + w) * HIDN + lane + 32 * i] = hh[i];
    }
}

// out[row][c] = s_z * sum_j H[row][j]*Wout[j][c]
#define OB_ROWS 64
#define HSTR    68
__global__ void __launch_bounds__(256, 2) nlnn_out(
    const float* __restrict__ Wout, const float* __restrict__ s_z_p,
    float* __restrict__ outp)
{
    extern __shared__ float sh[];                     // [256][HSTR]
    const int tid = threadIdx.x;
    const size_t row0 = (size_t)blockIdx.x * OB_ROWS;

#pragma unroll 8
    for (int i = 0; i < OB_ROWS; ++i)
        sh[tid * HSTR + i] = g_H[(row0 + i) * HIDN + tid];
    __syncthreads();

    const int c = tid & 63, rb = (tid >> 6) * 16;
    const float sz = s_z_p[0];

    u64t acc[8];
#pragma unroll
    for (int p = 0; p < 8; ++p) acc[p] = 0ull;

#pragma unroll 4
    for (int j = 0; j < HIDN; ++j) {
        u64t b = dup2(Wout[j * OUTN + c]);
        const float* hp = sh + j * HSTR + rb;
        ulonglong2 hA = *(const ulonglong2*)(hp);
        ulonglong2 hB = *(const ulonglong2*)(hp + 4);
        ulonglong2 hC = *(const ulonglong2*)(hp + 8);
        ulonglong2 hD = *(const ulonglong2*)(hp + 12);
        ffma2(acc[0], hA.x, b); ffma2(acc[1], hA.y, b);
        ffma2(acc[2], hB.x, b); ffma2(acc[3], hB.y, b);
        ffma2(acc[4], hC.x, b); ffma2(acc[5], hC.y, b);
        ffma2(acc[6], hD.x, b); ffma2(acc[7], hD.y, b);
    }
#pragma unroll
    for (int p = 0; p < 8; ++p) {
        size_t r = row0 + rb + 2 * p;
        outp[r * OUTN + c]       = sz * lo2(acc[p]);
        outp[(r + 1) * OUTN + c] = sz * hi2(acc[p]);
    }
}

extern "C" void kernel_launch(void* const* d_in, const int* in_sizes, int n_in,
                              void* d_out, int out_size) {
    const float* x      = (const float*)d_in[0];
    const float* h_init = (const float*)d_in[1];
    const float* Win    = (const float*)d_in[2];
    const float* Wrec   = (const float*)d_in[3];
    const float* Wout   = (const float*)d_in[4];
    const float* li     = (const float*)d_in[5];
    const float* lr     = (const float*)d_in[6];
    const float* sz     = (const float*)d_in[7];
    const float* ar     = (const float*)d_in[8];

    float* outp = (float*)d_out;
    long long main_elems = (long long)BATCHN * SEQN * OUTN;
    float* hfin = nullptr;
    if ((long long)out_size >= main_elems + (long long)BATCHN * HIDN)
        hfin = outp + main_elems;

    int smem_main = (HIDN * CSS + INPN * CSS + 4 * ROWS * HIDN + 4 * ROWS * HIDN)
                    * (int)sizeof(float);
    int smem_out  = (HIDN * HSTR) * (int)sizeof(float);
    cudaFuncSetAttribute(nlnn_main, cudaFuncAttributeMaxDynamicSharedMemorySize, smem_main);
    cudaFuncSetAttribute(nlnn_out,  cudaFuncAttributeMaxDynamicSharedMemorySize, smem_out);

    prep_kernel<<<HIDN + INPN, HIDN>>>(Win, Wrec, li, lr);
    nlnn_main<<<BATCHN / ROWS, NTHR, smem_main>>>(x, h_init, ar, hfin);
    nlnn_out<<<(BATCHN * SEQN) / OB_ROWS, 256, smem_out>>>(Wout, sz, outp);
}